// round 6
// baseline (speedup 1.0000x reference)
#include <cuda_runtime.h>

#define DIMC 192
#define BB   4
#define HH   256
#define WW   256
#define RR   48
#define KK9  9
#define EPSV 1e-5f

// Scratch (allocation-free rule: __device__ globals)
__device__ float g_pooled[BB * DIMC];       // [b*DIM + c]
__device__ float g_wt[BB * DIMC * KK9];     // [b*DIM*9 + c*9 + k]

// ---- 256-bit L2 eviction-hinted accesses (ptxas requires v8.b32 for hints) --
__device__ __forceinline__ void ld256_evict_last(const float* p, float* v) {
    asm volatile("ld.global.L2::evict_last.v8.b32 {%0,%1,%2,%3,%4,%5,%6,%7}, [%8];"
                 : "=f"(v[0]), "=f"(v[1]), "=f"(v[2]), "=f"(v[3]),
                   "=f"(v[4]), "=f"(v[5]), "=f"(v[6]), "=f"(v[7])
                 : "l"(p));
}
__device__ __forceinline__ void ld256_evict_first(const float* p, float* v) {
    asm volatile("ld.global.L2::evict_first.v8.b32 {%0,%1,%2,%3,%4,%5,%6,%7}, [%8];"
                 : "=f"(v[0]), "=f"(v[1]), "=f"(v[2]), "=f"(v[3]),
                   "=f"(v[4]), "=f"(v[5]), "=f"(v[6]), "=f"(v[7])
                 : "l"(p));
}
__device__ __forceinline__ void st256_evict_first(float* p, const float* v) {
    asm volatile("st.global.L2::evict_first.v8.b32 [%0], {%1,%2,%3,%4,%5,%6,%7,%8};"
                 :: "l"(p),
                    "f"(v[0]), "f"(v[1]), "f"(v[2]), "f"(v[3]),
                    "f"(v[4]), "f"(v[5]), "f"(v[6]), "f"(v[7])
                 : "memory");
}

// ---------------------------------------------------------------------------
// Kernel 1: global average pool per (b, c) plane. 768 blocks x 256 threads.
// 256-bit loads with evict_last: pin x in L2 for the conv pass (L2 survives
// launch boundaries; only L1 is flushed per launch).
// ---------------------------------------------------------------------------
__global__ __launch_bounds__(256) void pool_kernel(const float* __restrict__ x) {
    const int plane = blockIdx.x;  // b*DIM + c
    const float* __restrict__ p = x + (size_t)plane * HH * WW;
    const int tid = threadIdx.x;

    float s = 0.f;
    // 8192 float8 per plane / 256 threads = 32 per thread
    #pragma unroll 4
    for (int i = tid; i < (HH * WW) / 8; i += 256) {
        float v[8];
        ld256_evict_last(p + i * 8, v);
        s += ((v[0] + v[1]) + (v[2] + v[3])) + ((v[4] + v[5]) + (v[6] + v[7]));
    }

    __shared__ float sh[8];
    #pragma unroll
    for (int o = 16; o > 0; o >>= 1) s += __shfl_down_sync(0xffffffffu, s, o);
    if ((tid & 31) == 0) sh[tid >> 5] = s;
    __syncthreads();
    if (tid < 8) {
        float v = sh[tid];
        #pragma unroll
        for (int o = 4; o > 0; o >>= 1) v += __shfl_down_sync(0xffu, v, o);
        if (tid == 0) g_pooled[plane] = v * (1.0f / (HH * WW));
    }
}

// ---------------------------------------------------------------------------
// Kernel 2: dynamic weight MLP + BN(eval) + ReLU + mask. 27 blocks x 256 thr.
// ---------------------------------------------------------------------------
__global__ __launch_bounds__(256) void weights_kernel(
    const float* __restrict__ w1,
    const float* __restrict__ gamma,
    const float* __restrict__ beta,
    const float* __restrict__ rmean,
    const float* __restrict__ rvar,
    const float* __restrict__ w2,
    const float* __restrict__ b2) {
    __shared__ float tsh[BB * RR];  // 192
    const int tid = threadIdx.x;

    if (tid < BB * RR) {
        const int b = tid / RR, j = tid % RR;
        const float* __restrict__ pb = &g_pooled[b * DIMC];
        const float* __restrict__ wj = &w1[j * DIMC];
        float acc = 0.f;
        #pragma unroll 8
        for (int c = 0; c < DIMC; c++) acc = fmaf(pb[c], wj[c], acc);
        acc = gamma[j] * (acc - rmean[j]) * rsqrtf(rvar[j] + EPSV) + beta[j];
        tsh[tid] = fmaxf(acc, 0.f);
    }
    __syncthreads();

    const int i = blockIdx.x * 256 + tid;      // 0..6911
    const int b = i / (DIMC * KK9);
    const int o = i % (DIMC * KK9);
    const int kidx = o % KK9;
    const int krow = kidx / 3, kcol = kidx % 3;
    // mask 'A': zero (1,1),(1,2) and all of row 2
    const bool masked = (krow == 2) || (krow == 1 && kcol >= 1);
    float val = 0.f;
    if (!masked) {
        float acc = b2[o];
        const float* __restrict__ ts = &tsh[b * RR];
        const float* __restrict__ wr = &w2[(size_t)o * RR];
        #pragma unroll
        for (int j = 0; j < RR; j++) acc = fmaf(ts[j], wr[j], acc);
        val = acc;
    }
    g_wt[i] = val;
}

// ---------------------------------------------------------------------------
// Kernel 3: 4-tap causal depthwise conv, taps (0,0),(0,1),(0,2),(1,0), zero pad.
//   out[y][x] = w00*in[y-1][x-1] + w01*in[y-1][x] + w02*in[y-1][x+1]
//             + w10*in[y][x-1]   + bias[c]
// One block per plane; one WARP per row (32 lanes x 8 cols = 256). All halos
// via shfl — zero scalar loads. Per row: 1x LDG.256(evict_first) + 2 shfl +
// 32 FMA + 1x STG.256(evict_first). Previous row register-carried; each warp
// owns 32 consecutive rows.
// ---------------------------------------------------------------------------
__global__ __launch_bounds__(256) void conv_kernel(
    const float* __restrict__ x,
    const float* __restrict__ bias,
    float* __restrict__ out) {
    const int plane = blockIdx.x;         // b*DIM + c
    const int c = plane % DIMC;
    const float* __restrict__ wv = &g_wt[plane * KK9];
    const float w00 = wv[0], w01 = wv[1], w02 = wv[2], w10 = wv[3];
    const float bvv = bias[c];

    const float* __restrict__ in = x + (size_t)plane * HH * WW;
    float* __restrict__ op = out + (size_t)plane * HH * WW;

    const int tid  = threadIdx.x;
    const int warp = tid >> 5;      // 0..7: rows [warp*32, warp*32+32)
    const int lane = tid & 31;      // cols [lane*8, lane*8+8)
    const int col0 = lane * 8;
    const int y0   = warp * 32;

    // previous-row state
    float p[8];
    float pm1, pp8;
    if (warp == 0) {
        #pragma unroll
        for (int i = 0; i < 8; i++) p[i] = 0.f;
        pm1 = 0.f; pp8 = 0.f;
    } else {
        ld256_evict_first(in + (y0 - 1) * WW + col0, p);
        pm1 = __shfl_up_sync(0xffffffffu, p[7], 1);
        if (lane == 0) pm1 = 0.f;
        pp8 = __shfl_down_sync(0xffffffffu, p[0], 1);
        if (lane == 31) pp8 = 0.f;
    }

    #pragma unroll 4
    for (int y = y0; y < y0 + 32; y++) {
        float cv[8];
        ld256_evict_first(in + y * WW + col0, cv);

        // cm1 = in[y][col0-1] = neighbor lane's cv[7]
        float cm1 = __shfl_up_sync(0xffffffffu, cv[7], 1);
        if (lane == 0) cm1 = 0.f;

        float o[8];
        o[0] = fmaf(w00, pm1,  fmaf(w01, p[0], fmaf(w02, p[1], fmaf(w10, cm1,   bvv))));
        #pragma unroll
        for (int i = 1; i < 7; i++)
            o[i] = fmaf(w00, p[i-1], fmaf(w01, p[i], fmaf(w02, p[i+1], fmaf(w10, cv[i-1], bvv))));
        o[7] = fmaf(w00, p[6], fmaf(w01, p[7], fmaf(w02, pp8, fmaf(w10, cv[6], bvv))));

        st256_evict_first(op + y * WW + col0, o);

        // carry current row to next iteration
        float nx = __shfl_down_sync(0xffffffffu, cv[0], 1);
        if (lane == 31) nx = 0.f;
        pm1 = cm1;
        pp8 = nx;
        #pragma unroll
        for (int i = 0; i < 8; i++) p[i] = cv[i];
    }
}

// ---------------------------------------------------------------------------
// Launch. Inputs (metadata order):
//  0:x 1:w1 2:gamma 3:beta 4:running_mean 5:running_var 6:w2 7:b2 8:bias
// ---------------------------------------------------------------------------
extern "C" void kernel_launch(void* const* d_in, const int* in_sizes, int n_in,
                              void* d_out, int out_size) {
    const float* x     = (const float*)d_in[0];
    const float* w1    = (const float*)d_in[1];
    const float* gamma = (const float*)d_in[2];
    const float* beta  = (const float*)d_in[3];
    const float* rmean = (const float*)d_in[4];
    const float* rvar  = (const float*)d_in[5];
    const float* w2    = (const float*)d_in[6];
    const float* b2    = (const float*)d_in[7];
    const float* bias  = (const float*)d_in[8];
    float* out = (float*)d_out;

    pool_kernel<<<BB * DIMC, 256>>>(x);
    weights_kernel<<<(BB * DIMC * KK9) / 256, 256>>>(w1, gamma, beta, rmean, rvar, w2, b2);
    conv_kernel<<<BB * DIMC, 256>>>(x, bias, out);
}

// round 7
// speedup vs baseline: 1.0824x; 1.0824x over previous
#include <cuda_runtime.h>

#define DIMC 192
#define BB   4
#define HH   256
#define WW   256
#define RR   48
#define KK9  9
#define EPSV 1e-5f
#define NCTA 384            // 2 planes per CTA

// Scratch (allocation-free rule: __device__ globals; zero-initialized)
__device__ float g_pooled[BB * DIMC];
__device__ unsigned g_arrive;
__device__ unsigned g_done;

// ---- 256-bit L2 eviction-hinted accesses ----------------------------------
__device__ __forceinline__ void ld256_evict_last(const float* p, float* v) {
    asm volatile("ld.global.L2::evict_last.v8.b32 {%0,%1,%2,%3,%4,%5,%6,%7}, [%8];"
                 : "=f"(v[0]), "=f"(v[1]), "=f"(v[2]), "=f"(v[3]),
                   "=f"(v[4]), "=f"(v[5]), "=f"(v[6]), "=f"(v[7])
                 : "l"(p));
}
__device__ __forceinline__ void ld256_evict_first(const float* p, float* v) {
    asm volatile("ld.global.L2::evict_first.v8.b32 {%0,%1,%2,%3,%4,%5,%6,%7}, [%8];"
                 : "=f"(v[0]), "=f"(v[1]), "=f"(v[2]), "=f"(v[3]),
                   "=f"(v[4]), "=f"(v[5]), "=f"(v[6]), "=f"(v[7])
                 : "l"(p));
}
__device__ __forceinline__ void st256_evict_first(float* p, const float* v) {
    asm volatile("st.global.L2::evict_first.v8.b32 [%0], {%1,%2,%3,%4,%5,%6,%7,%8};"
                 :: "l"(p),
                    "f"(v[0]), "f"(v[1]), "f"(v[2]), "f"(v[3]),
                    "f"(v[4]), "f"(v[5]), "f"(v[6]), "f"(v[7])
                 : "memory");
}

// ---------------------------------------------------------------------------
// Fused kernel: pool(2 planes) -> grid barrier -> tiny MLP -> conv(2 planes).
// 384 CTAs x 256 threads; __launch_bounds__(256,4) guarantees co-residency
// (4 CTAs/SM x 148 SMs = 592 slots >= 384) so the spin barrier cannot deadlock.
// ---------------------------------------------------------------------------
__global__ __launch_bounds__(256, 4) void fused_kernel(
    const float* __restrict__ x,
    const float* __restrict__ w1,
    const float* __restrict__ gamma,
    const float* __restrict__ beta,
    const float* __restrict__ rmean,
    const float* __restrict__ rvar,
    const float* __restrict__ w2,
    const float* __restrict__ b2,
    const float* __restrict__ bias,
    float* __restrict__ out) {

    const int tid   = threadIdx.x;
    const int warp  = tid >> 5;
    const int lane  = tid & 31;
    const int pl0   = blockIdx.x * 2;       // planes pl0, pl0+1 (same batch b)
    const int b     = pl0 / DIMC;

    __shared__ float tsh[RR];      // hidden vector t[b][0..47]
    __shared__ float wsh[2][4];    // 4 live taps per plane
    __shared__ float red[8];       // pool reduction scratch

    // ---------------- Phase 1: pool both planes (evict_last pins x) --------
    #pragma unroll
    for (int pi = 0; pi < 2; pi++) {
        const float* __restrict__ p = x + (size_t)(pl0 + pi) * HH * WW;
        float s = 0.f;
        #pragma unroll 4
        for (int i = tid; i < (HH * WW) / 8; i += 256) {
            float v[8];
            ld256_evict_last(p + i * 8, v);
            s += ((v[0] + v[1]) + (v[2] + v[3])) + ((v[4] + v[5]) + (v[6] + v[7]));
        }
        #pragma unroll
        for (int o = 16; o > 0; o >>= 1) s += __shfl_down_sync(0xffffffffu, s, o);
        if (lane == 0) red[warp] = s;
        __syncthreads();
        if (tid < 8) {
            float v = red[tid];
            #pragma unroll
            for (int o = 4; o > 0; o >>= 1) v += __shfl_down_sync(0xffu, v, o);
            if (tid == 0) g_pooled[pl0 + pi] = v * (1.0f / (HH * WW));
        }
        __syncthreads();
    }

    // ---------------- Grid-wide barrier ------------------------------------
    if (tid == 0) {
        __threadfence();
        atomicAdd(&g_arrive, 1u);
        while (*(volatile unsigned*)&g_arrive < (unsigned)NCTA) { __nanosleep(64); }
        __threadfence();
    }
    __syncthreads();

    // ---------------- Phase 2: t[b] then this CTA's 8 taps ------------------
    if (tid < RR) {
        const float* __restrict__ pb = &g_pooled[b * DIMC];
        const float* __restrict__ wj = &w1[tid * DIMC];
        float acc = 0.f;
        #pragma unroll 8
        for (int c = 0; c < DIMC; c++) acc = fmaf(pb[c], wj[c], acc);
        acc = gamma[tid] * (acc - rmean[tid]) * rsqrtf(rvar[tid] + EPSV) + beta[tid];
        tsh[tid] = fmaxf(acc, 0.f);
    }
    __syncthreads();
    // live taps are exactly kidx 0..3: (0,0),(0,1),(0,2),(1,0)
    if (tid < 8) {
        const int pi  = tid >> 2;           // which of the 2 planes
        const int k   = tid & 3;            // tap 0..3
        const int c   = (pl0 + pi) % DIMC;
        const int o   = c * KK9 + k;        // row of w2 within batch (same for all b)
        float acc = b2[o];
        const float* __restrict__ wr = &w2[(size_t)o * RR];
        #pragma unroll
        for (int j = 0; j < RR; j++) acc = fmaf(tsh[j], wr[j], acc);
        wsh[pi][k] = acc;
    }
    __syncthreads();

    // ---------------- Phase 3: conv both planes, freshest first ------------
    #pragma unroll
    for (int pi = 1; pi >= 0; pi--) {
        const int plane = pl0 + pi;
        const float w00 = wsh[pi][0], w01 = wsh[pi][1],
                    w02 = wsh[pi][2], w10 = wsh[pi][3];
        const float bvv = bias[plane % DIMC];

        const float* __restrict__ in = x + (size_t)plane * HH * WW;
        float* __restrict__ op = out + (size_t)plane * HH * WW;

        const int col0 = lane * 8;      // 32 lanes x 8 cols = full row
        const int y0   = warp * 32;     // 8 warps x 32 rows

        float p[8];
        float pm1, pp8;
        if (warp == 0) {
            #pragma unroll
            for (int i = 0; i < 8; i++) p[i] = 0.f;
            pm1 = 0.f; pp8 = 0.f;
        } else {
            ld256_evict_first(in + (y0 - 1) * WW + col0, p);
            pm1 = __shfl_up_sync(0xffffffffu, p[7], 1);
            if (lane == 0) pm1 = 0.f;
            pp8 = __shfl_down_sync(0xffffffffu, p[0], 1);
            if (lane == 31) pp8 = 0.f;
        }

        #pragma unroll 4
        for (int y = y0; y < y0 + 32; y++) {
            float cv[8];
            ld256_evict_first(in + y * WW + col0, cv);

            float cm1 = __shfl_up_sync(0xffffffffu, cv[7], 1);
            if (lane == 0) cm1 = 0.f;

            float o[8];
            o[0] = fmaf(w00, pm1,  fmaf(w01, p[0], fmaf(w02, p[1], fmaf(w10, cm1, bvv))));
            #pragma unroll
            for (int i = 1; i < 7; i++)
                o[i] = fmaf(w00, p[i-1], fmaf(w01, p[i], fmaf(w02, p[i+1], fmaf(w10, cv[i-1], bvv))));
            o[7] = fmaf(w00, p[6], fmaf(w01, p[7], fmaf(w02, pp8, fmaf(w10, cv[6], bvv))));

            st256_evict_first(op + y * WW + col0, o);

            float nx = __shfl_down_sync(0xffffffffu, cv[0], 1);
            if (lane == 31) nx = 0.f;
            pm1 = cm1;
            pp8 = nx;
            #pragma unroll
            for (int i = 0; i < 8; i++) p[i] = cv[i];
        }
        __syncthreads();
    }

    // ---------------- Reset barrier counters for next graph replay ---------
    if (tid == 0) {
        unsigned d = atomicAdd(&g_done, 1u);
        if (d == (unsigned)(NCTA - 1)) {
            g_arrive = 0u;
            g_done = 0u;
            __threadfence();
        }
    }
}

// ---------------------------------------------------------------------------
// Launch. Inputs (metadata order):
//  0:x 1:w1 2:gamma 3:beta 4:running_mean 5:running_var 6:w2 7:b2 8:bias
// ---------------------------------------------------------------------------
extern "C" void kernel_launch(void* const* d_in, const int* in_sizes, int n_in,
                              void* d_out, int out_size) {
    const float* x     = (const float*)d_in[0];
    const float* w1    = (const float*)d_in[1];
    const float* gamma = (const float*)d_in[2];
    const float* beta  = (const float*)d_in[3];
    const float* rmean = (const float*)d_in[4];
    const float* rvar  = (const float*)d_in[5];
    const float* w2    = (const float*)d_in[6];
    const float* b2    = (const float*)d_in[7];
    const float* bias  = (const float*)d_in[8];
    float* out = (float*)d_out;

    fused_kernel<<<NCTA, 256>>>(x, w1, gamma, beta, rmean, rvar, w2, b2, bias, out);
}